// round 7
// baseline (speedup 1.0000x reference)
#include <cuda_runtime.h>
#include <cuda_bf16.h>
#include <math.h>
#include <stdint.h>

#define KK   4
#define NN   8192
#define BB   8
#define CC   64
#define HDIM 64
#define LL   4
#define EE   128
#define TC   61
#define EPSF 1e-6f
#define BN   (BB*NN)
#define SCALE 0.25f

__device__ float d_te[BB*TC];
__device__ float d_f0 [BN*CC];
__device__ float d_g0 [BN*CC];
__device__ float d_q0 [BN*CC];
__device__ float d_k0b[BN*CC];
__device__ float d_v0b[BN*CC];
__device__ float d_o0 [BN*CC];
__device__ float d_f1 [BN*3*CC];
__device__ float d_g1 [BN*3*CC];
__device__ float d_q1 [BN*3*CC];
__device__ float d_k1b[BN*3*CC];
__device__ float d_v1b[BN*3*CC];
__device__ float d_o1 [BN*3*CC];
__device__ float d_hb [BN*4*CC];
__device__ float d_rhat[BN*KK*3];

// te = silu(sin_embed(t) @ w1 + b1) @ w2 + b2
__global__ void te_kernel(const float* __restrict__ t,
                          const float* __restrict__ w1, const float* __restrict__ b1,
                          const float* __restrict__ w2, const float* __restrict__ b2)
{
    __shared__ float se[EE];
    __shared__ float h1[EE];
    int b = blockIdx.x, e = threadIdx.x;
    float tv = t[b];
    if (e < EE/2) {
        float fr  = expf(-logf(10000.f) * (float)e / (float)(EE/2));
        float emb = tv * fr;
        se[e]        = sinf(emb);
        se[e + EE/2] = cosf(emb);
    }
    __syncthreads();
    float acc = b1[e];
    #pragma unroll 8
    for (int i = 0; i < EE; i++) acc += se[i] * w1[i*EE + e];
    h1[e] = acc / (1.f + expf(-acc));
    __syncthreads();
    if (e < TC) {
        float o = b2[e];
        #pragma unroll 8
        for (int i = 0; i < EE; i++) o += h1[i] * w2[i*TC + e];
        d_te[b*TC + e] = o;
    }
}

// init f0 = [te | x], f1 = outer(x, win1), rhat
__global__ void init_kernel(const float* __restrict__ x, const int* __restrict__ nbr,
                            const float* __restrict__ win1)
{
    int tid = blockIdx.x * blockDim.x + threadIdx.x;
    if (tid >= BN*CC) return;
    int bn = tid >> 6, c = tid & 63;
    int b  = bn >> 13, n = bn & (NN-1);
    d_f0[tid] = (c < TC) ? d_te[b*TC + c] : x[(size_t)bn*3 + (c - TC)];
    float w = win1[c];
    #pragma unroll
    for (int v = 0; v < 3; v++)
        d_f1[((size_t)bn*3 + v)*CC + c] = x[(size_t)bn*3 + v] * w;
    if (c < KK) {
        int k = c;
        int idx = nbr[n*KK + k];
        int bj  = (b << 13) + idx;
        float r0 = x[(size_t)bj*3+0] - x[(size_t)bn*3+0];
        float r1 = x[(size_t)bj*3+1] - x[(size_t)bn*3+1];
        float r2 = x[(size_t)bj*3+2] - x[(size_t)bn*3+2];
        float s  = rsqrtf(r0*r0 + r1*r1 + r2*r2 + EPSF);
        d_rhat[((size_t)bn*KK + k)*3 + 0] = r0*s;
        d_rhat[((size_t)bn*KK + k)*3 + 1] = r1*s;
        d_rhat[((size_t)bn*KK + k)*3 + 2] = r2*s;
    }
}

// LayerNorm over C, warp per node
__global__ void ln_kernel(const float* __restrict__ in, float* __restrict__ out)
{
    int gt = blockIdx.x * blockDim.x + threadIdx.x;
    int w = gt >> 5;  if (w >= BN) return;
    int lane = gt & 31;
    const float* r = in + (size_t)w*CC;
    float a = r[lane], c = r[lane+32];
    float s = a + c, q = a*a + c*c;
    #pragma unroll
    for (int o = 16; o >= 1; o >>= 1) {
        s += __shfl_xor_sync(0xffffffffu, s, o);
        q += __shfl_xor_sync(0xffffffffu, q, o);
    }
    float mu  = s * (1.f/64.f);
    float var = q * (1.f/64.f) - mu*mu;
    float rs  = rsqrtf(var + EPSF);
    out[(size_t)w*CC + lane]    = (a - mu) * rs;
    out[(size_t)w*CC + lane+32] = (c - mu) * rs;
}

// vector norm over (C,v), warp per node
__global__ void vnorm_kernel(const float* __restrict__ in, float* __restrict__ out)
{
    int gt = blockIdx.x * blockDim.x + threadIdx.x;
    int w = gt >> 5;  if (w >= BN) return;
    int lane = gt & 31;
    const float* r = in + (size_t)w*3*CC;
    float vals[6]; float q = 0.f;
    #pragma unroll
    for (int v = 0; v < 3; v++) {
        float a = r[v*CC + lane], c = r[v*CC + lane + 32];
        vals[2*v] = a; vals[2*v+1] = c;
        q += a*a + c*c;
    }
    #pragma unroll
    for (int o = 16; o >= 1; o >>= 1) q += __shfl_xor_sync(0xffffffffu, q, o);
    float s = rsqrtf(q * (1.f/64.f) + EPSF);
    float* ow = out + (size_t)w*3*CC;
    #pragma unroll
    for (int v = 0; v < 3; v++) {
        ow[v*CC + lane]      = vals[2*v]   * s;
        ow[v*CC + lane + 32] = vals[2*v+1] * s;
    }
}

// generic SGEMM: C[M,N] (+)= act(A[M,Kd] @ Bw[Kd,N]); 64x64 tile, 64 threads, 8x8 micro
__global__ void gemm_kernel(const float* __restrict__ A, const float* __restrict__ Bw,
                            float* __restrict__ C, int M, int N, int Kd,
                            int doAcc, int doSilu)
{
    __shared__ float As[64][68];
    __shared__ float Bs[64][72];
    int m0 = blockIdx.x * 64;
    int n0 = blockIdx.y * 64;
    int tid = threadIdx.x;
    int tr = tid >> 3, tc = tid & 7;

    float acc[8][8];
    #pragma unroll
    for (int i = 0; i < 8; i++)
        #pragma unroll
        for (int j = 0; j < 8; j++) acc[i][j] = 0.f;

    for (int kp = 0; kp < Kd; kp += 64) {
        const float* arow = A + (size_t)(m0 + tid) * Kd + kp;
        #pragma unroll
        for (int i = 0; i < 16; i++) {
            float4 a4 = *reinterpret_cast<const float4*>(arow + i*4);
            As[i*4+0][tid] = a4.x;
            As[i*4+1][tid] = a4.y;
            As[i*4+2][tid] = a4.z;
            As[i*4+3][tid] = a4.w;
        }
        #pragma unroll
        for (int i = 0; i < 16; i++) {
            int q  = tid + i*64;
            int kk = q >> 4;
            int n4 = q & 15;
            float4 b4 = *reinterpret_cast<const float4*>(Bw + (size_t)(kp + kk) * N + n0 + n4*4);
            *reinterpret_cast<float4*>(&Bs[kk][n4*4]) = b4;
        }
        __syncthreads();

        #pragma unroll 16
        for (int k = 0; k < 64; k++) {
            float4 a0 = *reinterpret_cast<const float4*>(&As[k][tr*8]);
            float4 a1 = *reinterpret_cast<const float4*>(&As[k][tr*8 + 4]);
            float4 b0 = *reinterpret_cast<const float4*>(&Bs[k][tc*8]);
            float4 b1 = *reinterpret_cast<const float4*>(&Bs[k][tc*8 + 4]);
            float av[8] = {a0.x,a0.y,a0.z,a0.w,a1.x,a1.y,a1.z,a1.w};
            float bv[8] = {b0.x,b0.y,b0.z,b0.w,b1.x,b1.y,b1.z,b1.w};
            #pragma unroll
            for (int i = 0; i < 8; i++)
                #pragma unroll
                for (int j = 0; j < 8; j++)
                    acc[i][j] += av[i] * bv[j];
        }
        __syncthreads();
    }

    #pragma unroll
    for (int i = 0; i < 8; i++) {
        size_t m = (size_t)(m0 + tr*8 + i);
        float* crow = C + m * N + n0 + tc*8;
        float r[8];
        #pragma unroll
        for (int j = 0; j < 8; j++) {
            float v = acc[i][j];
            if (doSilu) v = v / (1.f + expf(-v));
            r[j] = v;
        }
        if (doAcc) {
            float4 c0 = *reinterpret_cast<const float4*>(crow);
            float4 c1 = *reinterpret_cast<const float4*>(crow + 4);
            r[0]+=c0.x; r[1]+=c0.y; r[2]+=c0.z; r[3]+=c0.w;
            r[4]+=c1.x; r[5]+=c1.y; r[6]+=c1.z; r[7]+=c1.w;
        }
        *reinterpret_cast<float4*>(crow)     = make_float4(r[0],r[1],r[2],r[3]);
        *reinterpret_cast<float4*>(crow + 4) = make_float4(r[4],r[5],r[6],r[7]);
    }
}

// attention, warp per node. lane owns channels {lane, lane+32}; head = channel>>4.
__global__ void attn_kernel(const int* __restrict__ nbr)
{
    int gt = blockIdx.x * blockDim.x + threadIdx.x;
    int w = gt >> 5;  if (w >= BN) return;
    int lane = gt & 31;
    int bn = w;
    int b = bn >> 13, n = bn & (NN-1);
    int e0 = lane, e1 = lane + 32;

    int js[KK]; float bias[KK];
    #pragma unroll
    for (int k = 0; k < KK; k++) {
        int idx = nbr[n*KK + k];
        js[k] = (b << 13) + idx;
        bool msk = (k == 0) || (idx != 0) || ((n == 1) && (k == 1));
        bias[k] = msk ? 0.f : -1e9f;
    }

    const float* q0r = d_q0 + (size_t)bn*CC;
    float q0a = q0r[e0], q0b = q0r[e1];
    float q1a[3], q1b[3];
    #pragma unroll
    for (int v = 0; v < 3; v++) {
        const float* r = d_q1 + ((size_t)bn*3 + v)*CC;
        q1a[v] = r[e0]; q1b[v] = r[e1];
    }

    float l0[KK], l1[KK];
    #pragma unroll
    for (int k = 0; k < KK; k++) {
        const float* k0r = d_k0b + (size_t)js[k]*CC;
        float p0 = q0a * k0r[e0];
        float p1 = q0b * k0r[e1];
        #pragma unroll
        for (int v = 0; v < 3; v++) {
            const float* k1r = d_k1b + ((size_t)js[k]*3 + v)*CC;
            p0 += q1a[v] * k1r[e0];
            p1 += q1b[v] * k1r[e1];
        }
        #pragma unroll
        for (int o = 8; o >= 1; o >>= 1) {   // reduce over D=16 within head group
            p0 += __shfl_xor_sync(0xffffffffu, p0, o);
            p1 += __shfl_xor_sync(0xffffffffu, p1, o);
        }
        l0[k] = p0 * SCALE + bias[k];
        l1[k] = p1 * SCALE + bias[k];
    }

    float m0v = fmaxf(fmaxf(l0[0], l0[1]), fmaxf(l0[2], l0[3]));
    float m1v = fmaxf(fmaxf(l1[0], l1[1]), fmaxf(l1[2], l1[3]));
    float a0[KK], a1[KK]; float s0 = 0.f, s1 = 0.f;
    #pragma unroll
    for (int k = 0; k < KK; k++) {
        a0[k] = expf(l0[k] - m0v); s0 += a0[k];
        a1[k] = expf(l1[k] - m1v); s1 += a1[k];
    }
    float i0 = 1.f / s0, i1 = 1.f / s1;
    #pragma unroll
    for (int k = 0; k < KK; k++) { a0[k] *= i0; a1[k] *= i1; }

    float o0a = 0.f, o0b = 0.f;
    float o1a[3] = {0.f,0.f,0.f}, o1b[3] = {0.f,0.f,0.f};
    #pragma unroll
    for (int k = 0; k < KK; k++) {
        const float* rh = d_rhat + ((size_t)bn*KK + k)*3;
        float rv0 = rh[0], rv1 = rh[1], rv2 = rh[2];
        float rv[3] = { rv0, rv1, rv2 };
        const float* v0r = d_v0b + (size_t)js[k]*CC;
        float va = v0r[e0], vb = v0r[e1];
        float sa = va, sb = vb;
        #pragma unroll
        for (int v = 0; v < 3; v++) {
            const float* v1r = d_v1b + ((size_t)js[k]*3 + v)*CC;
            float w1a = v1r[e0], w1b = v1r[e1];
            sa += w1a * rv[v];
            sb += w1b * rv[v];
            o1a[v] += a0[k] * (w1a + va * rv[v]);
            o1b[v] += a1[k] * (w1b + vb * rv[v]);
        }
        o0a += a0[k] * sa;
        o0b += a1[k] * sb;
    }
    d_o0[(size_t)bn*CC + e0] = o0a;
    d_o0[(size_t)bn*CC + e1] = o0b;
    #pragma unroll
    for (int v = 0; v < 3; v++) {
        d_o1[((size_t)bn*3 + v)*CC + e0] = o1a[v];
        d_o1[((size_t)bn*3 + v)*CC + e1] = o1b[v];
    }
}

// score = einsum('bncv,vc->bnv', f1, Wout) + bout
__global__ void out_kernel(const float* __restrict__ Wout, const float* __restrict__ bout,
                           float* __restrict__ out)
{
    int gt = blockIdx.x * blockDim.x + threadIdx.x;
    int w = gt >> 5;  if (w >= BN) return;
    int lane = gt & 31;
    float p0, p1, p2;
    {
        const float* fr = d_f1 + (size_t)w*3*CC;
        p0 = fr[0*CC+lane]*Wout[0*CC+lane] + fr[0*CC+lane+32]*Wout[0*CC+lane+32];
        p1 = fr[1*CC+lane]*Wout[1*CC+lane] + fr[1*CC+lane+32]*Wout[1*CC+lane+32];
        p2 = fr[2*CC+lane]*Wout[2*CC+lane] + fr[2*CC+lane+32]*Wout[2*CC+lane+32];
    }
    #pragma unroll
    for (int o = 16; o >= 1; o >>= 1) {
        p0 += __shfl_xor_sync(0xffffffffu, p0, o);
        p1 += __shfl_xor_sync(0xffffffffu, p1, o);
        p2 += __shfl_xor_sync(0xffffffffu, p2, o);
    }
    if (lane == 0) {
        out[(size_t)w*3 + 0] = p0 + bout[0];
        out[(size_t)w*3 + 1] = p1 + bout[1];
        out[(size_t)w*3 + 2] = p2 + bout[2];
    }
}

static inline void run_gemm(const float* A, const float* Bw, float* C,
                            int M, int N, int Kd, int acc, int silu)
{
    dim3 g(M/64, N/64);
    gemm_kernel<<<g, 64>>>(A, Bw, C, M, N, Kd, acc, silu);
}

extern "C" void kernel_launch(void* const* d_in, const int* in_sizes, int n_in,
                              void* d_out, int out_size)
{
    (void)in_sizes; (void)n_in; (void)out_size;
    const float* x     = (const float*)d_in[0];
    const float* t     = (const float*)d_in[2];
    const int*   nbr   = (const int*)  d_in[3];
    const float* t_w1  = (const float*)d_in[5];
    const float* t_b1  = (const float*)d_in[6];
    const float* t_w2  = (const float*)d_in[7];
    const float* t_b2  = (const float*)d_in[8];
    const float* win1  = (const float*)d_in[9];
    const float* Wq0   = (const float*)d_in[10];
    const float* Wk0   = (const float*)d_in[11];
    const float* Wv0   = (const float*)d_in[12];
    const float* Wq1   = (const float*)d_in[13];
    const float* Wk1   = (const float*)d_in[14];
    const float* Wv1   = (const float*)d_in[15];
    const float* Wo0   = (const float*)d_in[16];
    const float* Wo1   = (const float*)d_in[17];
    const float* Wff0a = (const float*)d_in[18];
    const float* Wff0b = (const float*)d_in[19];
    const float* Wff1  = (const float*)d_in[20];
    const float* Wout  = (const float*)d_in[21];
    const float* bout  = (const float*)d_in[22];
    float* out = (float*)d_out;

    float *f0,*f1,*g0,*g1,*q0,*k0,*v0,*q1,*k1,*v1,*o0,*o1,*hb;
    cudaGetSymbolAddress((void**)&f0, d_f0);
    cudaGetSymbolAddress((void**)&f1, d_f1);
    cudaGetSymbolAddress((void**)&g0, d_g0);
    cudaGetSymbolAddress((void**)&g1, d_g1);
    cudaGetSymbolAddress((void**)&q0, d_q0);
    cudaGetSymbolAddress((void**)&k0, d_k0b);
    cudaGetSymbolAddress((void**)&v0, d_v0b);
    cudaGetSymbolAddress((void**)&q1, d_q1);
    cudaGetSymbolAddress((void**)&k1, d_k1b);
    cudaGetSymbolAddress((void**)&v1, d_v1b);
    cudaGetSymbolAddress((void**)&o0, d_o0);
    cudaGetSymbolAddress((void**)&o1, d_o1);
    cudaGetSymbolAddress((void**)&hb, d_hb);

    te_kernel<<<BB, EE>>>(t, t_w1, t_b1, t_w2, t_b2);
    init_kernel<<<(BN*CC)/256, 256>>>(x, nbr, win1);

    const int NWBLK = (BN*32)/256;   // warp-per-node kernels

    for (int l = 0; l < LL; l++) {
        const float* wq0 = Wq0   + (size_t)l*CC*HDIM;
        const float* wk0 = Wk0   + (size_t)l*CC*HDIM;
        const float* wv0 = Wv0   + (size_t)l*CC*HDIM;
        const float* wq1 = Wq1   + (size_t)l*CC*HDIM;
        const float* wk1 = Wk1   + (size_t)l*CC*HDIM;
        const float* wv1 = Wv1   + (size_t)l*CC*HDIM;
        const float* wo0 = Wo0   + (size_t)l*HDIM*CC;
        const float* wo1 = Wo1   + (size_t)l*HDIM*CC;
        const float* wfa = Wff0a + (size_t)l*CC*4*CC;
        const float* wfb = Wff0b + (size_t)l*4*CC*CC;
        const float* wf1 = Wff1  + (size_t)l*CC*CC;

        ln_kernel   <<<NWBLK, 256>>>(f0, g0);
        vnorm_kernel<<<NWBLK, 256>>>(f1, g1);

        run_gemm(g0, wq0, q0, BN,   CC, CC, 0, 0);
        run_gemm(g0, wk0, k0, BN,   CC, CC, 0, 0);
        run_gemm(g0, wv0, v0, BN,   CC, CC, 0, 0);
        run_gemm(g1, wq1, q1, BN*3, CC, CC, 0, 0);
        run_gemm(g1, wk1, k1, BN*3, CC, CC, 0, 0);
        run_gemm(g1, wv1, v1, BN*3, CC, CC, 0, 0);

        attn_kernel<<<NWBLK, 256>>>(nbr);

        run_gemm(o0, wo0, f0, BN,   CC, CC, 1, 0);
        run_gemm(o1, wo1, f1, BN*3, CC, CC, 1, 0);

        ln_kernel<<<NWBLK, 256>>>(f0, g0);
        run_gemm(g0, wfa, hb, BN, 4*CC, CC,   0, 1);   // silu fused
        run_gemm(hb, wfb, f0, BN, CC,   4*CC, 1, 0);

        vnorm_kernel<<<NWBLK, 256>>>(f1, g1);
        run_gemm(g1, wf1, f1, BN*3, CC, CC, 1, 0);
    }

    out_kernel<<<NWBLK, 256>>>(Wout, bout, out);
}

// round 9
// speedup vs baseline: 1.2757x; 1.2757x over previous
#include <cuda_runtime.h>
#include <cuda_bf16.h>
#include <math.h>
#include <stdint.h>

#define KK   4
#define NN   8192
#define BB   8
#define CC   64
#define HDIM 64
#define LL   4
#define EE   128
#define TC   61
#define EPSF 1e-6f
#define BN   (BB*NN)
#define SCALE 0.25f

__device__ float d_te[BB*TC];
__device__ float d_f0 [BN*CC];
__device__ float d_g0 [BN*CC];
__device__ float d_q0 [BN*CC];
__device__ float d_k0b[BN*CC];
__device__ float d_v0b[BN*CC];
__device__ float d_o0 [BN*CC];
__device__ float d_f1 [BN*3*CC];
__device__ float d_g1 [BN*3*CC];
__device__ float d_q1 [BN*3*CC];
__device__ float d_k1b[BN*3*CC];
__device__ float d_v1b[BN*3*CC];
__device__ float d_o1 [BN*3*CC];
__device__ float d_hb [BN*4*CC];
__device__ float d_rhat[BN*KK*3];

// te = silu(sin_embed(t) @ w1 + b1) @ w2 + b2
__global__ void te_kernel(const float* __restrict__ t,
                          const float* __restrict__ w1, const float* __restrict__ b1,
                          const float* __restrict__ w2, const float* __restrict__ b2)
{
    __shared__ float se[EE];
    __shared__ float h1[EE];
    int b = blockIdx.x, e = threadIdx.x;
    float tv = t[b];
    if (e < EE/2) {
        float fr  = expf(-logf(10000.f) * (float)e / (float)(EE/2));
        float emb = tv * fr;
        se[e]        = sinf(emb);
        se[e + EE/2] = cosf(emb);
    }
    __syncthreads();
    float acc = b1[e];
    #pragma unroll 8
    for (int i = 0; i < EE; i++) acc += se[i] * w1[i*EE + e];
    h1[e] = acc / (1.f + expf(-acc));
    __syncthreads();
    if (e < TC) {
        float o = b2[e];
        #pragma unroll 8
        for (int i = 0; i < EE; i++) o += h1[i] * w2[i*TC + e];
        d_te[b*TC + e] = o;
    }
}

// init f0 = [te | x], f1 = outer(x, win1), rhat
__global__ void init_kernel(const float* __restrict__ x, const int* __restrict__ nbr,
                            const float* __restrict__ win1)
{
    int tid = blockIdx.x * blockDim.x + threadIdx.x;
    if (tid >= BN*CC) return;
    int bn = tid >> 6, c = tid & 63;
    int b  = bn >> 13, n = bn & (NN-1);
    d_f0[tid] = (c < TC) ? d_te[b*TC + c] : x[(size_t)bn*3 + (c - TC)];
    float w = win1[c];
    #pragma unroll
    for (int v = 0; v < 3; v++)
        d_f1[((size_t)bn*3 + v)*CC + c] = x[(size_t)bn*3 + v] * w;
    if (c < KK) {
        int k = c;
        int idx = nbr[n*KK + k];
        int bj  = (b << 13) + idx;
        float r0 = x[(size_t)bj*3+0] - x[(size_t)bn*3+0];
        float r1 = x[(size_t)bj*3+1] - x[(size_t)bn*3+1];
        float r2 = x[(size_t)bj*3+2] - x[(size_t)bn*3+2];
        float s  = rsqrtf(r0*r0 + r1*r1 + r2*r2 + EPSF);
        d_rhat[((size_t)bn*KK + k)*3 + 0] = r0*s;
        d_rhat[((size_t)bn*KK + k)*3 + 1] = r1*s;
        d_rhat[((size_t)bn*KK + k)*3 + 2] = r2*s;
    }
}

// LayerNorm over C, warp per node
__global__ void ln_kernel(const float* __restrict__ in, float* __restrict__ out)
{
    int gt = blockIdx.x * blockDim.x + threadIdx.x;
    int w = gt >> 5;  if (w >= BN) return;
    int lane = gt & 31;
    const float* r = in + (size_t)w*CC;
    float a = r[lane], c = r[lane+32];
    float s = a + c, q = a*a + c*c;
    #pragma unroll
    for (int o = 16; o >= 1; o >>= 1) {
        s += __shfl_xor_sync(0xffffffffu, s, o);
        q += __shfl_xor_sync(0xffffffffu, q, o);
    }
    float mu  = s * (1.f/64.f);
    float var = q * (1.f/64.f) - mu*mu;
    float rs  = rsqrtf(var + EPSF);
    out[(size_t)w*CC + lane]    = (a - mu) * rs;
    out[(size_t)w*CC + lane+32] = (c - mu) * rs;
}

// vector norm over (C,v), warp per node
__global__ void vnorm_kernel(const float* __restrict__ in, float* __restrict__ out)
{
    int gt = blockIdx.x * blockDim.x + threadIdx.x;
    int w = gt >> 5;  if (w >= BN) return;
    int lane = gt & 31;
    const float* r = in + (size_t)w*3*CC;
    float vals[6]; float q = 0.f;
    #pragma unroll
    for (int v = 0; v < 3; v++) {
        float a = r[v*CC + lane], c = r[v*CC + lane + 32];
        vals[2*v] = a; vals[2*v+1] = c;
        q += a*a + c*c;
    }
    #pragma unroll
    for (int o = 16; o >= 1; o >>= 1) q += __shfl_xor_sync(0xffffffffu, q, o);
    float s = rsqrtf(q * (1.f/64.f) + EPSF);
    float* ow = out + (size_t)w*3*CC;
    #pragma unroll
    for (int v = 0; v < 3; v++) {
        ow[v*CC + lane]      = vals[2*v]   * s;
        ow[v*CC + lane + 32] = vals[2*v+1] * s;
    }
}

// ---------------- packed-f32x2 SGEMM ----------------
// C[M,N] (+)= act(A[M,Kd] @ Bw[Kd,N])
// 128x64 tile, 128 threads, 8x8 micro-tile, accumulators as f32x2 pairs.
#define FFMA2(acc, ap, bp) \
    asm("fma.rn.f32x2 %0, %1, %2, %0;" : "+l"(acc) : "l"(ap), "l"(bp))
#define PACK2(dst, src) \
    asm("mov.b64 %0, {%1, %1};" : "=l"(dst) : "r"(__float_as_uint(src)))
#define UNPACK2(lo, hi, src) \
    asm("mov.b64 {%0, %1}, %2;" : "=r"(lo), "=r"(hi) : "l"(src))

__global__ __launch_bounds__(128) void gemm_kernel(
    const float* __restrict__ A, const float* __restrict__ Bw,
    float* __restrict__ C, int M, int N, int Kd, int doAcc, int doSilu)
{
    __shared__ float As[64][128];   // [k][m]
    __shared__ float Bs[64][64];    // [k][n]
    int m0 = blockIdx.x * 128;
    int n0 = blockIdx.y * 64;
    int tid = threadIdx.x;              // 0..127
    int tr = tid >> 3, tc = tid & 7;    // tr 0..15, tc 0..7

    unsigned long long acc[8][4];
    #pragma unroll
    for (int i = 0; i < 8; i++)
        #pragma unroll
        for (int j = 0; j < 4; j++) acc[i][j] = 0ull;

    for (int kp = 0; kp < Kd; kp += 64) {
        // A tile: thread loads its global row m0+tid, transposed into As[k][m]
        {
            const float* arow = A + (size_t)(m0 + tid) * Kd + kp;
            #pragma unroll
            for (int i = 0; i < 16; i++) {
                float4 a4 = *reinterpret_cast<const float4*>(arow + i*4);
                As[i*4+0][tid] = a4.x;
                As[i*4+1][tid] = a4.y;
                As[i*4+2][tid] = a4.z;
                As[i*4+3][tid] = a4.w;
            }
        }
        // B tile: 64x64 floats = 1024 float4, 8 per thread
        #pragma unroll
        for (int i = 0; i < 8; i++) {
            int q  = tid + i*128;
            int kk = q >> 4;
            int n4 = q & 15;
            float4 b4 = *reinterpret_cast<const float4*>(Bw + (size_t)(kp + kk) * N + n0 + n4*4);
            *reinterpret_cast<float4*>(&Bs[kk][n4*4]) = b4;
        }
        __syncthreads();

        #pragma unroll 8
        for (int k = 0; k < 64; k++) {
            float4 a0 = *reinterpret_cast<const float4*>(&As[k][tr*8]);
            float4 a1 = *reinterpret_cast<const float4*>(&As[k][tr*8 + 4]);
            ulonglong2 b0 = *reinterpret_cast<const ulonglong2*>(&Bs[k][tc*8]);
            ulonglong2 b1 = *reinterpret_cast<const ulonglong2*>(&Bs[k][tc*8 + 4]);
            float av[8] = {a0.x,a0.y,a0.z,a0.w,a1.x,a1.y,a1.z,a1.w};
            #pragma unroll
            for (int i = 0; i < 8; i++) {
                unsigned long long ap;
                PACK2(ap, av[i]);
                FFMA2(acc[i][0], ap, b0.x);
                FFMA2(acc[i][1], ap, b0.y);
                FFMA2(acc[i][2], ap, b1.x);
                FFMA2(acc[i][3], ap, b1.y);
            }
        }
        __syncthreads();
    }

    #pragma unroll
    for (int i = 0; i < 8; i++) {
        size_t m = (size_t)(m0 + tr*8 + i);
        float* crow = C + m * N + n0 + tc*8;
        float r[8];
        #pragma unroll
        for (int j = 0; j < 4; j++) {
            unsigned int lo, hi;
            UNPACK2(lo, hi, acc[i][j]);
            r[2*j]   = __uint_as_float(lo);
            r[2*j+1] = __uint_as_float(hi);
        }
        if (doSilu) {
            #pragma unroll
            for (int j = 0; j < 8; j++) r[j] = r[j] / (1.f + expf(-r[j]));
        }
        if (doAcc) {
            float4 c0 = *reinterpret_cast<const float4*>(crow);
            float4 c1 = *reinterpret_cast<const float4*>(crow + 4);
            r[0]+=c0.x; r[1]+=c0.y; r[2]+=c0.z; r[3]+=c0.w;
            r[4]+=c1.x; r[5]+=c1.y; r[6]+=c1.z; r[7]+=c1.w;
        }
        *reinterpret_cast<float4*>(crow)     = make_float4(r[0],r[1],r[2],r[3]);
        *reinterpret_cast<float4*>(crow + 4) = make_float4(r[4],r[5],r[6],r[7]);
    }
}

// attention, warp per node. lane owns channels {lane, lane+32}; head = channel>>4.
__global__ void attn_kernel(const int* __restrict__ nbr)
{
    int gt = blockIdx.x * blockDim.x + threadIdx.x;
    int w = gt >> 5;  if (w >= BN) return;
    int lane = gt & 31;
    int bn = w;
    int b = bn >> 13, n = bn & (NN-1);
    int e0 = lane, e1 = lane + 32;

    int js[KK]; float bias[KK];
    #pragma unroll
    for (int k = 0; k < KK; k++) {
        int idx = nbr[n*KK + k];
        js[k] = (b << 13) + idx;
        bool msk = (k == 0) || (idx != 0) || ((n == 1) && (k == 1));
        bias[k] = msk ? 0.f : -1e9f;
    }

    const float* q0r = d_q0 + (size_t)bn*CC;
    float q0a = q0r[e0], q0b = q0r[e1];
    float q1a[3], q1b[3];
    #pragma unroll
    for (int v = 0; v < 3; v++) {
        const float* r = d_q1 + ((size_t)bn*3 + v)*CC;
        q1a[v] = r[e0]; q1b[v] = r[e1];
    }

    float l0[KK], l1[KK];
    #pragma unroll
    for (int k = 0; k < KK; k++) {
        const float* k0r = d_k0b + (size_t)js[k]*CC;
        float p0 = q0a * k0r[e0];
        float p1 = q0b * k0r[e1];
        #pragma unroll
        for (int v = 0; v < 3; v++) {
            const float* k1r = d_k1b + ((size_t)js[k]*3 + v)*CC;
            p0 += q1a[v] * k1r[e0];
            p1 += q1b[v] * k1r[e1];
        }
        #pragma unroll
        for (int o = 8; o >= 1; o >>= 1) {   // reduce over D=16 within head group
            p0 += __shfl_xor_sync(0xffffffffu, p0, o);
            p1 += __shfl_xor_sync(0xffffffffu, p1, o);
        }
        l0[k] = p0 * SCALE + bias[k];
        l1[k] = p1 * SCALE + bias[k];
    }

    float m0v = fmaxf(fmaxf(l0[0], l0[1]), fmaxf(l0[2], l0[3]));
    float m1v = fmaxf(fmaxf(l1[0], l1[1]), fmaxf(l1[2], l1[3]));
    float a0[KK], a1[KK]; float s0 = 0.f, s1 = 0.f;
    #pragma unroll
    for (int k = 0; k < KK; k++) {
        a0[k] = expf(l0[k] - m0v); s0 += a0[k];
        a1[k] = expf(l1[k] - m1v); s1 += a1[k];
    }
    float i0 = 1.f / s0, i1 = 1.f / s1;
    #pragma unroll
    for (int k = 0; k < KK; k++) { a0[k] *= i0; a1[k] *= i1; }

    float o0a = 0.f, o0b = 0.f;
    float o1a[3] = {0.f,0.f,0.f}, o1b[3] = {0.f,0.f,0.f};
    #pragma unroll
    for (int k = 0; k < KK; k++) {
        const float* rh = d_rhat + ((size_t)bn*KK + k)*3;
        float rv[3] = { rh[0], rh[1], rh[2] };
        const float* v0r = d_v0b + (size_t)js[k]*CC;
        float va = v0r[e0], vb = v0r[e1];
        float sa = va, sb = vb;
        #pragma unroll
        for (int v = 0; v < 3; v++) {
            const float* v1r = d_v1b + ((size_t)js[k]*3 + v)*CC;
            float w1a = v1r[e0], w1b = v1r[e1];
            sa += w1a * rv[v];
            sb += w1b * rv[v];
            o1a[v] += a0[k] * (w1a + va * rv[v]);
            o1b[v] += a1[k] * (w1b + vb * rv[v]);
        }
        o0a += a0[k] * sa;
        o0b += a1[k] * sb;
    }
    d_o0[(size_t)bn*CC + e0] = o0a;
    d_o0[(size_t)bn*CC + e1] = o0b;
    #pragma unroll
    for (int v = 0; v < 3; v++) {
        d_o1[((size_t)bn*3 + v)*CC + e0] = o1a[v];
        d_o1[((size_t)bn*3 + v)*CC + e1] = o1b[v];
    }
}

// score = einsum('bncv,vc->bnv', f1, Wout) + bout
__global__ void out_kernel(const float* __restrict__ Wout, const float* __restrict__ bout,
                           float* __restrict__ out)
{
    int gt = blockIdx.x * blockDim.x + threadIdx.x;
    int w = gt >> 5;  if (w >= BN) return;
    int lane = gt & 31;
    float p0, p1, p2;
    {
        const float* fr = d_f1 + (size_t)w*3*CC;
        p0 = fr[0*CC+lane]*Wout[0*CC+lane] + fr[0*CC+lane+32]*Wout[0*CC+lane+32];
        p1 = fr[1*CC+lane]*Wout[1*CC+lane] + fr[1*CC+lane+32]*Wout[1*CC+lane+32];
        p2 = fr[2*CC+lane]*Wout[2*CC+lane] + fr[2*CC+lane+32]*Wout[2*CC+lane+32];
    }
    #pragma unroll
    for (int o = 16; o >= 1; o >>= 1) {
        p0 += __shfl_xor_sync(0xffffffffu, p0, o);
        p1 += __shfl_xor_sync(0xffffffffu, p1, o);
        p2 += __shfl_xor_sync(0xffffffffu, p2, o);
    }
    if (lane == 0) {
        out[(size_t)w*3 + 0] = p0 + bout[0];
        out[(size_t)w*3 + 1] = p1 + bout[1];
        out[(size_t)w*3 + 2] = p2 + bout[2];
    }
}

static inline void run_gemm(const float* A, const float* Bw, float* C,
                            int M, int N, int Kd, int acc, int silu)
{
    dim3 g(M/128, N/64);
    gemm_kernel<<<g, 128>>>(A, Bw, C, M, N, Kd, acc, silu);
}

extern "C" void kernel_launch(void* const* d_in, const int* in_sizes, int n_in,
                              void* d_out, int out_size)
{
    (void)in_sizes; (void)n_in; (void)out_size;
    const float* x     = (const float*)d_in[0];
    const float* t     = (const float*)d_in[2];
    const int*   nbr   = (const int*)  d_in[3];
    const float* t_w1  = (const float*)d_in[5];
    const float* t_b1  = (const float*)d_in[6];
    const float* t_w2  = (const float*)d_in[7];
    const float* t_b2  = (const float*)d_in[8];
    const float* win1  = (const float*)d_in[9];
    const float* Wq0   = (const float*)d_in[10];
    const float* Wk0   = (const float*)d_in[11];
    const float* Wv0   = (const float*)d_in[12];
    const float* Wq1   = (const float*)d_in[13];
    const float* Wk1   = (const float*)d_in[14];
    const float* Wv1   = (const float*)d_in[15];
    const float* Wo0   = (const float*)d_in[16];
    const float* Wo1   = (const float*)d_in[17];
    const float* Wff0a = (const float*)d_in[18];
    const float* Wff0b = (const float*)d_in[19];
    const float* Wff1  = (const float*)d_in[20];
    const float* Wout  = (const float*)d_in[21];
    const float* bout  = (const float*)d_in[22];
    float* out = (float*)d_out;

    float *f0,*f1,*g0,*g1,*q0,*k0,*v0,*q1,*k1,*v1,*o0,*o1,*hb;
    cudaGetSymbolAddress((void**)&f0, d_f0);
    cudaGetSymbolAddress((void**)&f1, d_f1);
    cudaGetSymbolAddress((void**)&g0, d_g0);
    cudaGetSymbolAddress((void**)&g1, d_g1);
    cudaGetSymbolAddress((void**)&q0, d_q0);
    cudaGetSymbolAddress((void**)&k0, d_k0b);
    cudaGetSymbolAddress((void**)&v0, d_v0b);
    cudaGetSymbolAddress((void**)&q1, d_q1);
    cudaGetSymbolAddress((void**)&k1, d_k1b);
    cudaGetSymbolAddress((void**)&v1, d_v1b);
    cudaGetSymbolAddress((void**)&o0, d_o0);
    cudaGetSymbolAddress((void**)&o1, d_o1);
    cudaGetSymbolAddress((void**)&hb, d_hb);

    te_kernel<<<BB, EE>>>(t, t_w1, t_b1, t_w2, t_b2);
    init_kernel<<<(BN*CC)/256, 256>>>(x, nbr, win1);

    const int NWBLK = (BN*32)/256;   // warp-per-node kernels

    for (int l = 0; l < LL; l++) {
        const float* wq0 = Wq0   + (size_t)l*CC*HDIM;
        const float* wk0 = Wk0   + (size_t)l*CC*HDIM;
        const float* wv0 = Wv0   + (size_t)l*CC*HDIM;
        const float* wq1 = Wq1   + (size_t)l*CC*HDIM;
        const float* wk1 = Wk1   + (size_t)l*CC*HDIM;
        const float* wv1 = Wv1   + (size_t)l*CC*HDIM;
        const float* wo0 = Wo0   + (size_t)l*HDIM*CC;
        const float* wo1 = Wo1   + (size_t)l*HDIM*CC;
        const float* wfa = Wff0a + (size_t)l*CC*4*CC;
        const float* wfb = Wff0b + (size_t)l*4*CC*CC;
        const float* wf1 = Wff1  + (size_t)l*CC*CC;

        ln_kernel   <<<NWBLK, 256>>>(f0, g0);
        vnorm_kernel<<<NWBLK, 256>>>(f1, g1);

        run_gemm(g0, wq0, q0, BN,   CC, CC, 0, 0);
        run_gemm(g0, wk0, k0, BN,   CC, CC, 0, 0);
        run_gemm(g0, wv0, v0, BN,   CC, CC, 0, 0);
        run_gemm(g1, wq1, q1, BN*3, CC, CC, 0, 0);
        run_gemm(g1, wk1, k1, BN*3, CC, CC, 0, 0);
        run_gemm(g1, wv1, v1, BN*3, CC, CC, 0, 0);

        attn_kernel<<<NWBLK, 256>>>(nbr);

        run_gemm(o0, wo0, f0, BN,   CC, CC, 1, 0);
        run_gemm(o1, wo1, f1, BN*3, CC, CC, 1, 0);

        ln_kernel<<<NWBLK, 256>>>(f0, g0);
        run_gemm(g0, wfa, hb, BN, 4*CC, CC,   0, 1);   // silu fused
        run_gemm(hb, wfb, f0, BN, CC,   4*CC, 1, 0);

        vnorm_kernel<<<NWBLK, 256>>>(f1, g1);
        run_gemm(g1, wf1, f1, BN*3, CC, CC, 1, 0);
    }

    out_kernel<<<NWBLK, 256>>>(Wout, bout, out);
}

// round 10
// speedup vs baseline: 1.4034x; 1.1001x over previous
#include <cuda_runtime.h>
#include <cuda_bf16.h>
#include <math.h>
#include <stdint.h>

#define KK   4
#define NN   8192
#define BB   8
#define CC   64
#define HDIM 64
#define LL   4
#define EE   128
#define TC   61
#define EPSF 1e-6f
#define BN   (BB*NN)
#define SCALE 0.25f

__device__ float d_te[BB*TC];
__device__ float d_f0 [BN*CC];
__device__ float d_q0 [BN*CC];
__device__ float d_k0b[BN*CC];
__device__ float d_v0b[BN*CC];
__device__ float d_o0 [BN*CC];
__device__ float d_f1 [BN*3*CC];
__device__ float d_q1 [BN*3*CC];
__device__ float d_k1b[BN*3*CC];
__device__ float d_v1b[BN*3*CC];
__device__ float d_o1 [BN*3*CC];
__device__ float d_hb [BN*4*CC];
__device__ float d_rhat[BN*KK*3];
__device__ float d_vs [BN];

// te = silu(sin_embed(t) @ w1 + b1) @ w2 + b2
__global__ void te_kernel(const float* __restrict__ t,
                          const float* __restrict__ w1, const float* __restrict__ b1,
                          const float* __restrict__ w2, const float* __restrict__ b2)
{
    __shared__ float se[EE];
    __shared__ float h1[EE];
    int b = blockIdx.x, e = threadIdx.x;
    float tv = t[b];
    if (e < EE/2) {
        float fr  = expf(-logf(10000.f) * (float)e / (float)(EE/2));
        float emb = tv * fr;
        se[e]        = sinf(emb);
        se[e + EE/2] = cosf(emb);
    }
    __syncthreads();
    float acc = b1[e];
    #pragma unroll 8
    for (int i = 0; i < EE; i++) acc += se[i] * w1[i*EE + e];
    h1[e] = acc / (1.f + expf(-acc));
    __syncthreads();
    if (e < TC) {
        float o = b2[e];
        #pragma unroll 8
        for (int i = 0; i < EE; i++) o += h1[i] * w2[i*TC + e];
        d_te[b*TC + e] = o;
    }
}

// init f0 = [te | x], f1 = outer(x, win1), rhat
__global__ void init_kernel(const float* __restrict__ x, const int* __restrict__ nbr,
                            const float* __restrict__ win1)
{
    int tid = blockIdx.x * blockDim.x + threadIdx.x;
    if (tid >= BN*CC) return;
    int bn = tid >> 6, c = tid & 63;
    int b  = bn >> 13, n = bn & (NN-1);
    d_f0[tid] = (c < TC) ? d_te[b*TC + c] : x[(size_t)bn*3 + (c - TC)];
    float w = win1[c];
    #pragma unroll
    for (int v = 0; v < 3; v++)
        d_f1[((size_t)bn*3 + v)*CC + c] = x[(size_t)bn*3 + v] * w;
    if (c < KK) {
        int k = c;
        int idx = nbr[n*KK + k];
        int bj  = (b << 13) + idx;
        float r0 = x[(size_t)bj*3+0] - x[(size_t)bn*3+0];
        float r1 = x[(size_t)bj*3+1] - x[(size_t)bn*3+1];
        float r2 = x[(size_t)bj*3+2] - x[(size_t)bn*3+2];
        float s  = rsqrtf(r0*r0 + r1*r1 + r2*r2 + EPSF);
        d_rhat[((size_t)bn*KK + k)*3 + 0] = r0*s;
        d_rhat[((size_t)bn*KK + k)*3 + 1] = r1*s;
        d_rhat[((size_t)bn*KK + k)*3 + 2] = r2*s;
    }
}

// per-node vnorm scale: vs[n] = rsqrt(mean_c(sum_v f1^2) + eps)
__global__ void vscale_kernel(const float* __restrict__ in, float* __restrict__ vs)
{
    int gt = blockIdx.x * blockDim.x + threadIdx.x;
    int w = gt >> 5;  if (w >= BN) return;
    int lane = gt & 31;
    const float* r = in + (size_t)w*3*CC;
    float q = 0.f;
    #pragma unroll
    for (int v = 0; v < 3; v++) {
        float a = r[v*CC + lane], c = r[v*CC + lane + 32];
        q += a*a + c*c;
    }
    #pragma unroll
    for (int o = 16; o >= 1; o >>= 1) q += __shfl_xor_sync(0xffffffffu, q, o);
    if (lane == 0) vs[w] = rsqrtf(q * (1.f/64.f) + EPSF);
}

// ---------------- packed-f32x2 SGEMM with fused input norm ----------------
// For z = blockIdx.z: C_z[M,N] (+)= act(norm(A)[M,Kd] @ B_z[Kd,N])
// normMode: 0 = none, 1 = LayerNorm per row (requires Kd==64),
//           2 = scale row m by vs[m/3]
#define FFMA2(acc, ap, bp) \
    asm("fma.rn.f32x2 %0, %1, %2, %0;" : "+l"(acc) : "l"(ap), "l"(bp))
#define PACK2(dst, src) \
    asm("mov.b64 %0, {%1, %1};" : "=l"(dst) : "r"(__float_as_uint(src)))
#define UNPACK2(lo, hi, src) \
    asm("mov.b64 {%0, %1}, %2;" : "=r"(lo), "=r"(hi) : "l"(src))

__global__ __launch_bounds__(128) void gemm_kernel(
    const float* __restrict__ A,
    const float* __restrict__ B0, const float* __restrict__ B1, const float* __restrict__ B2,
    float* __restrict__ C0, float* __restrict__ C1, float* __restrict__ C2,
    const float* __restrict__ vs,
    int M, int N, int Kd, int doAcc, int doSilu, int normMode)
{
    __shared__ float As[64][128];   // [k][m]
    __shared__ float Bs[64][64];    // [k][n]
    int z = blockIdx.z;
    const float* Bw = (z == 0) ? B0 : ((z == 1) ? B1 : B2);
    float*       C  = (z == 0) ? C0 : ((z == 1) ? C1 : C2);

    int m0 = blockIdx.x * 128;
    int n0 = blockIdx.y * 64;
    int tid = threadIdx.x;              // 0..127
    int tr = tid >> 3, tc = tid & 7;

    unsigned long long acc[8][4];
    #pragma unroll
    for (int i = 0; i < 8; i++)
        #pragma unroll
        for (int j = 0; j < 4; j++) acc[i][j] = 0ull;

    for (int kp = 0; kp < Kd; kp += 64) {
        // A tile: thread owns global row m0+tid, transposed into As[k][m]
        {
            const float* arow = A + (size_t)(m0 + tid) * Kd + kp;
            if (normMode == 1) {
                float s = 0.f, q = 0.f;
                #pragma unroll
                for (int i = 0; i < 16; i++) {
                    float4 a4 = *reinterpret_cast<const float4*>(arow + i*4);
                    s += a4.x + a4.y + a4.z + a4.w;
                    q += a4.x*a4.x + a4.y*a4.y + a4.z*a4.z + a4.w*a4.w;
                    As[i*4+0][tid] = a4.x;
                    As[i*4+1][tid] = a4.y;
                    As[i*4+2][tid] = a4.z;
                    As[i*4+3][tid] = a4.w;
                }
                float mu  = s * (1.f/64.f);
                float var = q * (1.f/64.f) - mu*mu;
                float rs  = rsqrtf(var + EPSF);
                // fix up own column (only this thread wrote it)
                #pragma unroll
                for (int k = 0; k < 64; k++)
                    As[k][tid] = (As[k][tid] - mu) * rs;
            } else if (normMode == 2) {
                float sc = vs[(m0 + tid) / 3];
                #pragma unroll
                for (int i = 0; i < 16; i++) {
                    float4 a4 = *reinterpret_cast<const float4*>(arow + i*4);
                    As[i*4+0][tid] = a4.x * sc;
                    As[i*4+1][tid] = a4.y * sc;
                    As[i*4+2][tid] = a4.z * sc;
                    As[i*4+3][tid] = a4.w * sc;
                }
            } else {
                #pragma unroll
                for (int i = 0; i < 16; i++) {
                    float4 a4 = *reinterpret_cast<const float4*>(arow + i*4);
                    As[i*4+0][tid] = a4.x;
                    As[i*4+1][tid] = a4.y;
                    As[i*4+2][tid] = a4.z;
                    As[i*4+3][tid] = a4.w;
                }
            }
        }
        // B tile: 64x64 floats = 1024 float4, 8 per thread
        #pragma unroll
        for (int i = 0; i < 8; i++) {
            int q  = tid + i*128;
            int kk = q >> 4;
            int n4 = q & 15;
            float4 b4 = *reinterpret_cast<const float4*>(Bw + (size_t)(kp + kk) * N + n0 + n4*4);
            *reinterpret_cast<float4*>(&Bs[kk][n4*4]) = b4;
        }
        __syncthreads();

        #pragma unroll 8
        for (int k = 0; k < 64; k++) {
            float4 a0 = *reinterpret_cast<const float4*>(&As[k][tr*8]);
            float4 a1 = *reinterpret_cast<const float4*>(&As[k][tr*8 + 4]);
            ulonglong2 b0 = *reinterpret_cast<const ulonglong2*>(&Bs[k][tc*8]);
            ulonglong2 b1 = *reinterpret_cast<const ulonglong2*>(&Bs[k][tc*8 + 4]);
            float av[8] = {a0.x,a0.y,a0.z,a0.w,a1.x,a1.y,a1.z,a1.w};
            #pragma unroll
            for (int i = 0; i < 8; i++) {
                unsigned long long ap;
                PACK2(ap, av[i]);
                FFMA2(acc[i][0], ap, b0.x);
                FFMA2(acc[i][1], ap, b0.y);
                FFMA2(acc[i][2], ap, b1.x);
                FFMA2(acc[i][3], ap, b1.y);
            }
        }
        __syncthreads();
    }

    #pragma unroll
    for (int i = 0; i < 8; i++) {
        size_t m = (size_t)(m0 + tr*8 + i);
        float* crow = C + m * N + n0 + tc*8;
        float r[8];
        #pragma unroll
        for (int j = 0; j < 4; j++) {
            unsigned int lo, hi;
            UNPACK2(lo, hi, acc[i][j]);
            r[2*j]   = __uint_as_float(lo);
            r[2*j+1] = __uint_as_float(hi);
        }
        if (doSilu) {
            #pragma unroll
            for (int j = 0; j < 8; j++) r[j] = r[j] / (1.f + expf(-r[j]));
        }
        if (doAcc) {
            float4 c0 = *reinterpret_cast<const float4*>(crow);
            float4 c1 = *reinterpret_cast<const float4*>(crow + 4);
            r[0]+=c0.x; r[1]+=c0.y; r[2]+=c0.z; r[3]+=c0.w;
            r[4]+=c1.x; r[5]+=c1.y; r[6]+=c1.z; r[7]+=c1.w;
        }
        *reinterpret_cast<float4*>(crow)     = make_float4(r[0],r[1],r[2],r[3]);
        *reinterpret_cast<float4*>(crow + 4) = make_float4(r[4],r[5],r[6],r[7]);
    }
}

// attention, warp per node. lane owns channels {lane, lane+32}; head = channel>>4.
__global__ void attn_kernel(const int* __restrict__ nbr)
{
    int gt = blockIdx.x * blockDim.x + threadIdx.x;
    int w = gt >> 5;  if (w >= BN) return;
    int lane = gt & 31;
    int bn = w;
    int b = bn >> 13, n = bn & (NN-1);
    int e0 = lane, e1 = lane + 32;

    int js[KK]; float bias[KK];
    #pragma unroll
    for (int k = 0; k < KK; k++) {
        int idx = nbr[n*KK + k];
        js[k] = (b << 13) + idx;
        bool msk = (k == 0) || (idx != 0) || ((n == 1) && (k == 1));
        bias[k] = msk ? 0.f : -1e9f;
    }

    const float* q0r = d_q0 + (size_t)bn*CC;
    float q0a = q0r[e0], q0b = q0r[e1];
    float q1a[3], q1b[3];
    #pragma unroll
    for (int v = 0; v < 3; v++) {
        const float* r = d_q1 + ((size_t)bn*3 + v)*CC;
        q1a[v] = r[e0]; q1b[v] = r[e1];
    }

    float l0[KK], l1[KK];
    #pragma unroll
    for (int k = 0; k < KK; k++) {
        const float* k0r = d_k0b + (size_t)js[k]*CC;
        float p0 = q0a * k0r[e0];
        float p1 = q0b * k0r[e1];
        #pragma unroll
        for (int v = 0; v < 3; v++) {
            const float* k1r = d_k1b + ((size_t)js[k]*3 + v)*CC;
            p0 += q1a[v] * k1r[e0];
            p1 += q1b[v] * k1r[e1];
        }
        #pragma unroll
        for (int o = 8; o >= 1; o >>= 1) {   // reduce over D=16 within head group
            p0 += __shfl_xor_sync(0xffffffffu, p0, o);
            p1 += __shfl_xor_sync(0xffffffffu, p1, o);
        }
        l0[k] = p0 * SCALE + bias[k];
        l1[k] = p1 * SCALE + bias[k];
    }

    float m0v = fmaxf(fmaxf(l0[0], l0[1]), fmaxf(l0[2], l0[3]));
    float m1v = fmaxf(fmaxf(l1[0], l1[1]), fmaxf(l1[2], l1[3]));
    float a0[KK], a1[KK]; float s0 = 0.f, s1 = 0.f;
    #pragma unroll
    for (int k = 0; k < KK; k++) {
        a0[k] = expf(l0[k] - m0v); s0 += a0[k];
        a1[k] = expf(l1[k] - m1v); s1 += a1[k];
    }
    float i0 = 1.f / s0, i1 = 1.f / s1;
    #pragma unroll
    for (int k = 0; k < KK; k++) { a0[k] *= i0; a1[k] *= i1; }

    float o0a = 0.f, o0b = 0.f;
    float o1a[3] = {0.f,0.f,0.f}, o1b[3] = {0.f,0.f,0.f};
    #pragma unroll
    for (int k = 0; k < KK; k++) {
        const float* rh = d_rhat + ((size_t)bn*KK + k)*3;
        float rv[3] = { rh[0], rh[1], rh[2] };
        const float* v0r = d_v0b + (size_t)js[k]*CC;
        float va = v0r[e0], vb = v0r[e1];
        float sa = va, sb = vb;
        #pragma unroll
        for (int v = 0; v < 3; v++) {
            const float* v1r = d_v1b + ((size_t)js[k]*3 + v)*CC;
            float w1a = v1r[e0], w1b = v1r[e1];
            sa += w1a * rv[v];
            sb += w1b * rv[v];
            o1a[v] += a0[k] * (w1a + va * rv[v]);
            o1b[v] += a1[k] * (w1b + vb * rv[v]);
        }
        o0a += a0[k] * sa;
        o0b += a1[k] * sb;
    }
    d_o0[(size_t)bn*CC + e0] = o0a;
    d_o0[(size_t)bn*CC + e1] = o0b;
    #pragma unroll
    for (int v = 0; v < 3; v++) {
        d_o1[((size_t)bn*3 + v)*CC + e0] = o1a[v];
        d_o1[((size_t)bn*3 + v)*CC + e1] = o1b[v];
    }
}

// score = einsum('bncv,vc->bnv', f1, Wout) + bout
__global__ void out_kernel(const float* __restrict__ Wout, const float* __restrict__ bout,
                           float* __restrict__ out)
{
    int gt = blockIdx.x * blockDim.x + threadIdx.x;
    int w = gt >> 5;  if (w >= BN) return;
    int lane = gt & 31;
    float p0, p1, p2;
    {
        const float* fr = d_f1 + (size_t)w*3*CC;
        p0 = fr[0*CC+lane]*Wout[0*CC+lane] + fr[0*CC+lane+32]*Wout[0*CC+lane+32];
        p1 = fr[1*CC+lane]*Wout[1*CC+lane] + fr[1*CC+lane+32]*Wout[1*CC+lane+32];
        p2 = fr[2*CC+lane]*Wout[2*CC+lane] + fr[2*CC+lane+32]*Wout[2*CC+lane+32];
    }
    #pragma unroll
    for (int o = 16; o >= 1; o >>= 1) {
        p0 += __shfl_xor_sync(0xffffffffu, p0, o);
        p1 += __shfl_xor_sync(0xffffffffu, p1, o);
        p2 += __shfl_xor_sync(0xffffffffu, p2, o);
    }
    if (lane == 0) {
        out[(size_t)w*3 + 0] = p0 + bout[0];
        out[(size_t)w*3 + 1] = p1 + bout[1];
        out[(size_t)w*3 + 2] = p2 + bout[2];
    }
}

static inline void run_gemm3(const float* A,
                             const float* B0, const float* B1, const float* B2,
                             float* C0, float* C1, float* C2,
                             const float* vs, int M, int N, int Kd,
                             int acc, int silu, int norm, int nz)
{
    dim3 g(M/128, N/64, nz);
    gemm_kernel<<<g, 128>>>(A, B0, B1, B2, C0, C1, C2, vs, M, N, Kd, acc, silu, norm);
}

extern "C" void kernel_launch(void* const* d_in, const int* in_sizes, int n_in,
                              void* d_out, int out_size)
{
    (void)in_sizes; (void)n_in; (void)out_size;
    const float* x     = (const float*)d_in[0];
    const float* t     = (const float*)d_in[2];
    const int*   nbr   = (const int*)  d_in[3];
    const float* t_w1  = (const float*)d_in[5];
    const float* t_b1  = (const float*)d_in[6];
    const float* t_w2  = (const float*)d_in[7];
    const float* t_b2  = (const float*)d_in[8];
    const float* win1  = (const float*)d_in[9];
    const float* Wq0   = (const float*)d_in[10];
    const float* Wk0   = (const float*)d_in[11];
    const float* Wv0   = (const float*)d_in[12];
    const float* Wq1   = (const float*)d_in[13];
    const float* Wk1   = (const float*)d_in[14];
    const float* Wv1   = (const float*)d_in[15];
    const float* Wo0   = (const float*)d_in[16];
    const float* Wo1   = (const float*)d_in[17];
    const float* Wff0a = (const float*)d_in[18];
    const float* Wff0b = (const float*)d_in[19];
    const float* Wff1  = (const float*)d_in[20];
    const float* Wout  = (const float*)d_in[21];
    const float* bout  = (const float*)d_in[22];
    float* out = (float*)d_out;

    float *f0,*f1,*q0,*k0,*v0,*q1,*k1,*v1,*o0,*o1,*hb,*vsp;
    cudaGetSymbolAddress((void**)&f0,  d_f0);
    cudaGetSymbolAddress((void**)&f1,  d_f1);
    cudaGetSymbolAddress((void**)&q0,  d_q0);
    cudaGetSymbolAddress((void**)&k0,  d_k0b);
    cudaGetSymbolAddress((void**)&v0,  d_v0b);
    cudaGetSymbolAddress((void**)&q1,  d_q1);
    cudaGetSymbolAddress((void**)&k1,  d_k1b);
    cudaGetSymbolAddress((void**)&v1,  d_v1b);
    cudaGetSymbolAddress((void**)&o0,  d_o0);
    cudaGetSymbolAddress((void**)&o1,  d_o1);
    cudaGetSymbolAddress((void**)&hb,  d_hb);
    cudaGetSymbolAddress((void**)&vsp, d_vs);

    te_kernel<<<BB, EE>>>(t, t_w1, t_b1, t_w2, t_b2);
    init_kernel<<<(BN*CC)/256, 256>>>(x, nbr, win1);

    const int NWBLK = (BN*32)/256;   // warp-per-node kernels

    for (int l = 0; l < LL; l++) {
        const float* wq0 = Wq0   + (size_t)l*CC*HDIM;
        const float* wk0 = Wk0   + (size_t)l*CC*HDIM;
        const float* wv0 = Wv0   + (size_t)l*CC*HDIM;
        const float* wq1 = Wq1   + (size_t)l*CC*HDIM;
        const float* wk1 = Wk1   + (size_t)l*CC*HDIM;
        const float* wv1 = Wv1   + (size_t)l*CC*HDIM;
        const float* wo0 = Wo0   + (size_t)l*HDIM*CC;
        const float* wo1 = Wo1   + (size_t)l*HDIM*CC;
        const float* wfa = Wff0a + (size_t)l*CC*4*CC;
        const float* wfb = Wff0b + (size_t)l*4*CC*CC;
        const float* wf1 = Wff1  + (size_t)l*CC*CC;

        vscale_kernel<<<NWBLK, 256>>>(f1, vsp);

        // q/k/v for scalar features: LN fused into A-load
        run_gemm3(f0, wq0, wk0, wv0, q0, k0, v0, vsp, BN,   CC, CC, 0, 0, 1, 3);
        // q/k/v for vector features: vnorm scale fused into A-load
        run_gemm3(f1, wq1, wk1, wv1, q1, k1, v1, vsp, BN*3, CC, CC, 0, 0, 2, 3);

        attn_kernel<<<NWBLK, 256>>>(nbr);

        run_gemm3(o0, wo0, wo0, wo0, f0, f0, f0, vsp, BN,   CC, CC, 1, 0, 0, 1);
        run_gemm3(o1, wo1, wo1, wo1, f1, f1, f1, vsp, BN*3, CC, CC, 1, 0, 0, 1);

        // FF scalar: LN fused into A-load of first GEMM, silu fused into epilogue
        run_gemm3(f0, wfa, wfa, wfa, hb, hb, hb, vsp, BN, 4*CC, CC,   0, 1, 1, 1);
        run_gemm3(hb, wfb, wfb, wfb, f0, f0, f0, vsp, BN, CC,   4*CC, 1, 0, 0, 1);

        // FF vector: vnorm scale fused
        vscale_kernel<<<NWBLK, 256>>>(f1, vsp);
        run_gemm3(f1, wf1, wf1, wf1, f1, f1, f1, vsp, BN*3, CC, CC, 1, 0, 2, 1);
    }

    out_kernel<<<NWBLK, 256>>>(Wout, bout, out);
}

// round 11
// speedup vs baseline: 1.6208x; 1.1549x over previous
#include <cuda_runtime.h>
#include <cuda_bf16.h>
#include <math.h>
#include <stdint.h>

#define KK   4
#define NN   8192
#define BB   8
#define CC   64
#define HDIM 64
#define LL   4
#define EE   128
#define TC   61
#define EPSF 1e-6f
#define BN   (BB*NN)
#define SCALE 0.25f

__device__ float d_te[BB*TC];
__device__ float d_f0 [BN*CC];
__device__ float d_q0 [BN*CC];
__device__ float d_k0b[BN*CC];
__device__ float d_v0b[BN*CC];
__device__ float d_o0 [BN*CC];
__device__ float d_f1 [BN*3*CC];
__device__ float d_q1 [BN*3*CC];
__device__ float d_k1b[BN*3*CC];
__device__ float d_v1b[BN*3*CC];
__device__ float d_o1 [BN*3*CC];
__device__ float d_hb [BN*4*CC];
__device__ float d_rhat[BN*KK*3];
__device__ float d_vs [BN];

// te = silu(sin_embed(t) @ w1 + b1) @ w2 + b2
__global__ void te_kernel(const float* __restrict__ t,
                          const float* __restrict__ w1, const float* __restrict__ b1,
                          const float* __restrict__ w2, const float* __restrict__ b2)
{
    __shared__ float se[EE];
    __shared__ float h1[EE];
    int b = blockIdx.x, e = threadIdx.x;
    float tv = t[b];
    if (e < EE/2) {
        float fr  = expf(-logf(10000.f) * (float)e / (float)(EE/2));
        float emb = tv * fr;
        se[e]        = sinf(emb);
        se[e + EE/2] = cosf(emb);
    }
    __syncthreads();
    float acc = b1[e];
    #pragma unroll 8
    for (int i = 0; i < EE; i++) acc += se[i] * w1[i*EE + e];
    h1[e] = acc / (1.f + expf(-acc));
    __syncthreads();
    if (e < TC) {
        float o = b2[e];
        #pragma unroll 8
        for (int i = 0; i < EE; i++) o += h1[i] * w2[i*TC + e];
        d_te[b*TC + e] = o;
    }
}

// init f0 = [te | x], f1 = outer(x, win1), rhat
__global__ void init_kernel(const float* __restrict__ x, const int* __restrict__ nbr,
                            const float* __restrict__ win1)
{
    int tid = blockIdx.x * blockDim.x + threadIdx.x;
    if (tid >= BN*CC) return;
    int bn = tid >> 6, c = tid & 63;
    int b  = bn >> 13, n = bn & (NN-1);
    d_f0[tid] = (c < TC) ? d_te[b*TC + c] : x[(size_t)bn*3 + (c - TC)];
    float w = win1[c];
    #pragma unroll
    for (int v = 0; v < 3; v++)
        d_f1[((size_t)bn*3 + v)*CC + c] = x[(size_t)bn*3 + v] * w;
    if (c < KK) {
        int k = c;
        int idx = nbr[n*KK + k];
        int bj  = (b << 13) + idx;
        float r0 = x[(size_t)bj*3+0] - x[(size_t)bn*3+0];
        float r1 = x[(size_t)bj*3+1] - x[(size_t)bn*3+1];
        float r2 = x[(size_t)bj*3+2] - x[(size_t)bn*3+2];
        float s  = rsqrtf(r0*r0 + r1*r1 + r2*r2 + EPSF);
        d_rhat[((size_t)bn*KK + k)*3 + 0] = r0*s;
        d_rhat[((size_t)bn*KK + k)*3 + 1] = r1*s;
        d_rhat[((size_t)bn*KK + k)*3 + 2] = r2*s;
    }
}

// per-node vnorm scale: vs[n] = rsqrt(mean_c(sum_v f1^2) + eps)
__global__ void vscale_kernel(const float* __restrict__ in, float* __restrict__ vs)
{
    int gt = blockIdx.x * blockDim.x + threadIdx.x;
    int w = gt >> 5;  if (w >= BN) return;
    int lane = gt & 31;
    const float* r = in + (size_t)w*3*CC;
    float q = 0.f;
    #pragma unroll
    for (int v = 0; v < 3; v++) {
        float a = r[v*CC + lane], c = r[v*CC + lane + 32];
        q += a*a + c*c;
    }
    #pragma unroll
    for (int o = 16; o >= 1; o >>= 1) q += __shfl_xor_sync(0xffffffffu, q, o);
    if (lane == 0) vs[w] = rsqrtf(q * (1.f/64.f) + EPSF);
}

// ---------------- packed-f32x2 SGEMM with fused input norm ----------------
// For z = blockIdx.z: C_z[M,N] (+)= act(norm(A)[M,Kd] @ B_z[Kd,N])
// normMode: 0 = none, 1 = LayerNorm per row (requires Kd==64),
//           2 = scale row m by vs[m/3]
// Thread (tr,tc) owns rows tr*8..+8 and columns {4tc..4tc+3, 32+4tc..32+4tc+3}
// (split column ownership keeps the two B LDS.128 per k-step bank-conflict-free).
#define FFMA2(acc, ap, bp) \
    asm("fma.rn.f32x2 %0, %1, %2, %0;" : "+l"(acc) : "l"(ap), "l"(bp))
#define PACK2(dst, src) \
    asm("mov.b64 %0, {%1, %1};" : "=l"(dst) : "r"(__float_as_uint(src)))
#define UNPACK2(lo, hi, src) \
    asm("mov.b64 {%0, %1}, %2;" : "=r"(lo), "=r"(hi) : "l"(src))

__global__ __launch_bounds__(128, 4) void gemm_kernel(
    const float* __restrict__ A,
    const float* __restrict__ B0, const float* __restrict__ B1, const float* __restrict__ B2,
    float* __restrict__ C0, float* __restrict__ C1, float* __restrict__ C2,
    const float* __restrict__ vs,
    int M, int N, int Kd, int doAcc, int doSilu, int normMode)
{
    __shared__ float As[64][128];   // [k][m]
    __shared__ float Bs[64][64];    // [k][n]
    int z = blockIdx.z;
    const float* Bw = (z == 0) ? B0 : ((z == 1) ? B1 : B2);
    float*       C  = (z == 0) ? C0 : ((z == 1) ? C1 : C2);

    int m0 = blockIdx.x * 128;
    int n0 = blockIdx.y * 64;
    int tid = threadIdx.x;              // 0..127
    int tr = tid >> 3, tc = tid & 7;

    unsigned long long acc[8][4];
    #pragma unroll
    for (int i = 0; i < 8; i++)
        #pragma unroll
        for (int j = 0; j < 4; j++) acc[i][j] = 0ull;

    for (int kp = 0; kp < Kd; kp += 64) {
        // A tile: thread owns global row m0+tid, transposed into As[k][m]
        {
            const float* arow = A + (size_t)(m0 + tid) * Kd + kp;
            if (normMode == 1) {
                // pass 1: stats only (Kd==64, single slab)
                float s = 0.f, q = 0.f;
                #pragma unroll 8
                for (int i = 0; i < 16; i++) {
                    float4 a4 = *reinterpret_cast<const float4*>(arow + i*4);
                    s += a4.x + a4.y + a4.z + a4.w;
                    q += a4.x*a4.x + a4.y*a4.y + a4.z*a4.z + a4.w*a4.w;
                }
                float mu  = s * (1.f/64.f);
                float var = q * (1.f/64.f) - mu*mu;
                float rs  = rsqrtf(var + EPSF);
                // pass 2: reload (L1-hit) and store normalized
                #pragma unroll 8
                for (int i = 0; i < 16; i++) {
                    float4 a4 = *reinterpret_cast<const float4*>(arow + i*4);
                    As[i*4+0][tid] = (a4.x - mu) * rs;
                    As[i*4+1][tid] = (a4.y - mu) * rs;
                    As[i*4+2][tid] = (a4.z - mu) * rs;
                    As[i*4+3][tid] = (a4.w - mu) * rs;
                }
            } else if (normMode == 2) {
                float sc = vs[(m0 + tid) / 3];
                #pragma unroll 8
                for (int i = 0; i < 16; i++) {
                    float4 a4 = *reinterpret_cast<const float4*>(arow + i*4);
                    As[i*4+0][tid] = a4.x * sc;
                    As[i*4+1][tid] = a4.y * sc;
                    As[i*4+2][tid] = a4.z * sc;
                    As[i*4+3][tid] = a4.w * sc;
                }
            } else {
                #pragma unroll 8
                for (int i = 0; i < 16; i++) {
                    float4 a4 = *reinterpret_cast<const float4*>(arow + i*4);
                    As[i*4+0][tid] = a4.x;
                    As[i*4+1][tid] = a4.y;
                    As[i*4+2][tid] = a4.z;
                    As[i*4+3][tid] = a4.w;
                }
            }
        }
        // B tile: 64x64 floats = 1024 float4, 8 per thread
        #pragma unroll 8
        for (int i = 0; i < 8; i++) {
            int q  = tid + i*128;
            int kk = q >> 4;
            int n4 = q & 15;
            float4 b4 = *reinterpret_cast<const float4*>(Bw + (size_t)(kp + kk) * N + n0 + n4*4);
            *reinterpret_cast<float4*>(&Bs[kk][n4*4]) = b4;
        }
        __syncthreads();

        #pragma unroll 8
        for (int k = 0; k < 64; k++) {
            float4 a0 = *reinterpret_cast<const float4*>(&As[k][tr*8]);
            float4 a1 = *reinterpret_cast<const float4*>(&As[k][tr*8 + 4]);
            // conflict-free: 8 tc x 16B = 128B per load phase
            ulonglong2 b0 = *reinterpret_cast<const ulonglong2*>(&Bs[k][tc*4]);
            ulonglong2 b1 = *reinterpret_cast<const ulonglong2*>(&Bs[k][32 + tc*4]);
            float av[8] = {a0.x,a0.y,a0.z,a0.w,a1.x,a1.y,a1.z,a1.w};
            #pragma unroll
            for (int i = 0; i < 8; i++) {
                unsigned long long ap;
                PACK2(ap, av[i]);
                FFMA2(acc[i][0], ap, b0.x);
                FFMA2(acc[i][1], ap, b0.y);
                FFMA2(acc[i][2], ap, b1.x);
                FFMA2(acc[i][3], ap, b1.y);
            }
        }
        __syncthreads();
    }

    #pragma unroll
    for (int i = 0; i < 8; i++) {
        size_t m = (size_t)(m0 + tr*8 + i);
        float* ca = C + m * N + n0 + tc*4;        // cols 4tc..4tc+3
        float* cb = ca + 32;                       // cols 32+4tc..+3
        float r[8];
        #pragma unroll
        for (int j = 0; j < 4; j++) {
            unsigned int lo, hi;
            UNPACK2(lo, hi, acc[i][j]);
            r[2*j]   = __uint_as_float(lo);
            r[2*j+1] = __uint_as_float(hi);
        }
        if (doSilu) {
            #pragma unroll
            for (int j = 0; j < 8; j++) r[j] = r[j] / (1.f + expf(-r[j]));
        }
        if (doAcc) {
            float4 c0 = *reinterpret_cast<const float4*>(ca);
            float4 c1 = *reinterpret_cast<const float4*>(cb);
            r[0]+=c0.x; r[1]+=c0.y; r[2]+=c0.z; r[3]+=c0.w;
            r[4]+=c1.x; r[5]+=c1.y; r[6]+=c1.z; r[7]+=c1.w;
        }
        *reinterpret_cast<float4*>(ca) = make_float4(r[0],r[1],r[2],r[3]);
        *reinterpret_cast<float4*>(cb) = make_float4(r[4],r[5],r[6],r[7]);
    }
}

// attention, warp per node. lane owns channels {lane, lane+32}; head = channel>>4.
__global__ void attn_kernel(const int* __restrict__ nbr)
{
    int gt = blockIdx.x * blockDim.x + threadIdx.x;
    int w = gt >> 5;  if (w >= BN) return;
    int lane = gt & 31;
    int bn = w;
    int b = bn >> 13, n = bn & (NN-1);
    int e0 = lane, e1 = lane + 32;

    int js[KK]; float bias[KK];
    #pragma unroll
    for (int k = 0; k < KK; k++) {
        int idx = nbr[n*KK + k];
        js[k] = (b << 13) + idx;
        bool msk = (k == 0) || (idx != 0) || ((n == 1) && (k == 1));
        bias[k] = msk ? 0.f : -1e9f;
    }

    const float* q0r = d_q0 + (size_t)bn*CC;
    float q0a = q0r[e0], q0b = q0r[e1];
    float q1a[3], q1b[3];
    #pragma unroll
    for (int v = 0; v < 3; v++) {
        const float* r = d_q1 + ((size_t)bn*3 + v)*CC;
        q1a[v] = r[e0]; q1b[v] = r[e1];
    }

    float l0[KK], l1[KK];
    #pragma unroll
    for (int k = 0; k < KK; k++) {
        const float* k0r = d_k0b + (size_t)js[k]*CC;
        float p0 = q0a * k0r[e0];
        float p1 = q0b * k0r[e1];
        #pragma unroll
        for (int v = 0; v < 3; v++) {
            const float* k1r = d_k1b + ((size_t)js[k]*3 + v)*CC;
            p0 += q1a[v] * k1r[e0];
            p1 += q1b[v] * k1r[e1];
        }
        #pragma unroll
        for (int o = 8; o >= 1; o >>= 1) {   // reduce over D=16 within head group
            p0 += __shfl_xor_sync(0xffffffffu, p0, o);
            p1 += __shfl_xor_sync(0xffffffffu, p1, o);
        }
        l0[k] = p0 * SCALE + bias[k];
        l1[k] = p1 * SCALE + bias[k];
    }

    float m0v = fmaxf(fmaxf(l0[0], l0[1]), fmaxf(l0[2], l0[3]));
    float m1v = fmaxf(fmaxf(l1[0], l1[1]), fmaxf(l1[2], l1[3]));
    float a0[KK], a1[KK]; float s0 = 0.f, s1 = 0.f;
    #pragma unroll
    for (int k = 0; k < KK; k++) {
        a0[k] = expf(l0[k] - m0v); s0 += a0[k];
        a1[k] = expf(l1[k] - m1v); s1 += a1[k];
    }
    float i0 = 1.f / s0, i1 = 1.f / s1;
    #pragma unroll
    for (int k = 0; k < KK; k++) { a0[k] *= i0; a1[k] *= i1; }

    float o0a = 0.f, o0b = 0.f;
    float o1a[3] = {0.f,0.f,0.f}, o1b[3] = {0.f,0.f,0.f};
    #pragma unroll
    for (int k = 0; k < KK; k++) {
        const float* rh = d_rhat + ((size_t)bn*KK + k)*3;
        float rv[3] = { rh[0], rh[1], rh[2] };
        const float* v0r = d_v0b + (size_t)js[k]*CC;
        float va = v0r[e0], vb = v0r[e1];
        float sa = va, sb = vb;
        #pragma unroll
        for (int v = 0; v < 3; v++) {
            const float* v1r = d_v1b + ((size_t)js[k]*3 + v)*CC;
            float w1a = v1r[e0], w1b = v1r[e1];
            sa += w1a * rv[v];
            sb += w1b * rv[v];
            o1a[v] += a0[k] * (w1a + va * rv[v]);
            o1b[v] += a1[k] * (w1b + vb * rv[v]);
        }
        o0a += a0[k] * sa;
        o0b += a1[k] * sb;
    }
    d_o0[(size_t)bn*CC + e0] = o0a;
    d_o0[(size_t)bn*CC + e1] = o0b;
    #pragma unroll
    for (int v = 0; v < 3; v++) {
        d_o1[((size_t)bn*3 + v)*CC + e0] = o1a[v];
        d_o1[((size_t)bn*3 + v)*CC + e1] = o1b[v];
    }
}

// score = einsum('bncv,vc->bnv', f1, Wout) + bout
__global__ void out_kernel(const float* __restrict__ Wout, const float* __restrict__ bout,
                           float* __restrict__ out)
{
    int gt = blockIdx.x * blockDim.x + threadIdx.x;
    int w = gt >> 5;  if (w >= BN) return;
    int lane = gt & 31;
    float p0, p1, p2;
    {
        const float* fr = d_f1 + (size_t)w*3*CC;
        p0 = fr[0*CC+lane]*Wout[0*CC+lane] + fr[0*CC+lane+32]*Wout[0*CC+lane+32];
        p1 = fr[1*CC+lane]*Wout[1*CC+lane] + fr[1*CC+lane+32]*Wout[1*CC+lane+32];
        p2 = fr[2*CC+lane]*Wout[2*CC+lane] + fr[2*CC+lane+32]*Wout[2*CC+lane+32];
    }
    #pragma unroll
    for (int o = 16; o >= 1; o >>= 1) {
        p0 += __shfl_xor_sync(0xffffffffu, p0, o);
        p1 += __shfl_xor_sync(0xffffffffu, p1, o);
        p2 += __shfl_xor_sync(0xffffffffu, p2, o);
    }
    if (lane == 0) {
        out[(size_t)w*3 + 0] = p0 + bout[0];
        out[(size_t)w*3 + 1] = p1 + bout[1];
        out[(size_t)w*3 + 2] = p2 + bout[2];
    }
}

static inline void run_gemm3(const float* A,
                             const float* B0, const float* B1, const float* B2,
                             float* C0, float* C1, float* C2,
                             const float* vs, int M, int N, int Kd,
                             int acc, int silu, int norm, int nz)
{
    dim3 g(M/128, N/64, nz);
    gemm_kernel<<<g, 128>>>(A, B0, B1, B2, C0, C1, C2, vs, M, N, Kd, acc, silu, norm);
}

extern "C" void kernel_launch(void* const* d_in, const int* in_sizes, int n_in,
                              void* d_out, int out_size)
{
    (void)in_sizes; (void)n_in; (void)out_size;
    const float* x     = (const float*)d_in[0];
    const float* t     = (const float*)d_in[2];
    const int*   nbr   = (const int*)  d_in[3];
    const float* t_w1  = (const float*)d_in[5];
    const float* t_b1  = (const float*)d_in[6];
    const float* t_w2  = (const float*)d_in[7];
    const float* t_b2  = (const float*)d_in[8];
    const float* win1  = (const float*)d_in[9];
    const float* Wq0   = (const float*)d_in[10];
    const float* Wk0   = (const float*)d_in[11];
    const float* Wv0   = (const float*)d_in[12];
    const float* Wq1   = (const float*)d_in[13];
    const float* Wk1   = (const float*)d_in[14];
    const float* Wv1   = (const float*)d_in[15];
    const float* Wo0   = (const float*)d_in[16];
    const float* Wo1   = (const float*)d_in[17];
    const float* Wff0a = (const float*)d_in[18];
    const float* Wff0b = (const float*)d_in[19];
    const float* Wff1  = (const float*)d_in[20];
    const float* Wout  = (const float*)d_in[21];
    const float* bout  = (const float*)d_in[22];
    float* out = (float*)d_out;

    float *f0,*f1,*q0,*k0,*v0,*q1,*k1,*v1,*o0,*o1,*hb,*vsp;
    cudaGetSymbolAddress((void**)&f0,  d_f0);
    cudaGetSymbolAddress((void**)&f1,  d_f1);
    cudaGetSymbolAddress((void**)&q0,  d_q0);
    cudaGetSymbolAddress((void**)&k0,  d_k0b);
    cudaGetSymbolAddress((void**)&v0,  d_v0b);
    cudaGetSymbolAddress((void**)&q1,  d_q1);
    cudaGetSymbolAddress((void**)&k1,  d_k1b);
    cudaGetSymbolAddress((void**)&v1,  d_v1b);
    cudaGetSymbolAddress((void**)&o0,  d_o0);
    cudaGetSymbolAddress((void**)&o1,  d_o1);
    cudaGetSymbolAddress((void**)&hb,  d_hb);
    cudaGetSymbolAddress((void**)&vsp, d_vs);

    te_kernel<<<BB, EE>>>(t, t_w1, t_b1, t_w2, t_b2);
    init_kernel<<<(BN*CC)/256, 256>>>(x, nbr, win1);

    const int NWBLK = (BN*32)/256;   // warp-per-node kernels

    for (int l = 0; l < LL; l++) {
        const float* wq0 = Wq0   + (size_t)l*CC*HDIM;
        const float* wk0 = Wk0   + (size_t)l*CC*HDIM;
        const float* wv0 = Wv0   + (size_t)l*CC*HDIM;
        const float* wq1 = Wq1   + (size_t)l*CC*HDIM;
        const float* wk1 = Wk1   + (size_t)l*CC*HDIM;
        const float* wv1 = Wv1   + (size_t)l*CC*HDIM;
        const float* wo0 = Wo0   + (size_t)l*HDIM*CC;
        const float* wo1 = Wo1   + (size_t)l*HDIM*CC;
        const float* wfa = Wff0a + (size_t)l*CC*4*CC;
        const float* wfb = Wff0b + (size_t)l*4*CC*CC;
        const float* wf1 = Wff1  + (size_t)l*CC*CC;

        vscale_kernel<<<NWBLK, 256>>>(f1, vsp);

        // q/k/v scalar: LN fused into A-load
        run_gemm3(f0, wq0, wk0, wv0, q0, k0, v0, vsp, BN,   CC, CC, 0, 0, 1, 3);
        // q/k/v vector: vnorm scale fused into A-load
        run_gemm3(f1, wq1, wk1, wv1, q1, k1, v1, vsp, BN*3, CC, CC, 0, 0, 2, 3);

        attn_kernel<<<NWBLK, 256>>>(nbr);

        run_gemm3(o0, wo0, wo0, wo0, f0, f0, f0, vsp, BN,   CC, CC, 1, 0, 0, 1);
        run_gemm3(o1, wo1, wo1, wo1, f1, f1, f1, vsp, BN*3, CC, CC, 1, 0, 0, 1);

        // FF scalar: LN fused into first GEMM, silu fused into its epilogue
        run_gemm3(f0, wfa, wfa, wfa, hb, hb, hb, vsp, BN, 4*CC, CC,   0, 1, 1, 1);
        run_gemm3(hb, wfb, wfb, wfb, f0, f0, f0, vsp, BN, CC,   4*CC, 1, 0, 0, 1);

        // FF vector: vnorm scale fused
        vscale_kernel<<<NWBLK, 256>>>(f1, vsp);
        run_gemm3(f1, wf1, wf1, wf1, f1, f1, f1, vsp, BN*3, CC, CC, 1, 0, 2, 1);
    }

    out_kernel<<<NWBLK, 256>>>(Wout, bout, out);
}